// round 1
// baseline (speedup 1.0000x reference)
#include <cuda_runtime.h>
#include <cstdint>

// Problem constants (D=20, RANK=2 -> o=19 per axis, m=32)
#define O      19
#define DM     20
#define MM     32
#define ROWP   36                    // padded row (floats) -> conflict-free LDS.128
#define CT_STRIDE (MM*ROWP)          // 1152 floats per cos-table slab
#define NT     320                   // 10 warps
#define NWARP  10

typedef unsigned long long ull;

// ---- packed f32x2 helpers (sm_103a FFMA2 path, PTX-only) ----
__device__ __forceinline__ ull f2mul(ull a, ull b) {
    ull r; asm("mul.rn.f32x2 %0, %1, %2;" : "=l"(r) : "l"(a), "l"(b)); return r;
}
__device__ __forceinline__ ull f2fma(ull a, ull b, ull c) {
    ull r; asm("fma.rn.f32x2 %0, %1, %2, %3;" : "=l"(r) : "l"(a), "l"(b), "l"(c)); return r;
}
__device__ __forceinline__ float f2sum(ull v) {
    return __uint_as_float((unsigned)v) + __uint_as_float((unsigned)(v >> 32));
}

// Shared memory layout (floats):
//   Ct  [19][32][36]  @ 0       (21888)  Ct[n][i][j] = cos(2*pi*n / (32*i + j + 2))
//   R   [20][20][32]  @ 21888   (12800)  (a,b)-pair sum of hypervol
//   Gab [32][36]      @ 34688   (1152)   P[i][j]*Ct[a][i][j]*Ct[b][i][j]
//   WS  [10][2][32]   @ 35840   (640)    per-warp window-sum staging
//   X   [10][2][32]   @ 36480   (640)    per-warp x staging
// total 37120 floats = 148480 bytes
#define CT_OFF   0
#define R_OFF    21888
#define GAB_OFF  34688
#define WS_OFF   35840
#define X_OFF    36480
#define SMEM_BYTES (37120 * 4)

__global__ void __launch_bounds__(NT)
pm4_kernel(const float* __restrict__ H,   // [20,20,20,20,32]
           const float* __restrict__ Mw,  // [32,32]
           const float* __restrict__ P,   // [32,32]
           float* __restrict__ out)       // [19^4, 32]
{
    extern __shared__ float s[];
    float* Ct  = s + CT_OFF;
    float* R   = s + R_OFF;
    float* Gab = s + GAB_OFF;
    float* WSs = s + WS_OFF;
    float* Xs  = s + X_OFF;

    const int tid  = threadIdx.x;
    const int lane = tid & 31;
    const int w    = tid >> 5;
    const int ab   = blockIdx.x;
    const int A    = ab / O;
    const int B    = ab % O;

    const float TWO_PI = 6.28318530717958647692f;

    // ---- Phase 1a: cos table ----
    for (int e = tid; e < O * MM * MM; e += NT) {
        int n = e >> 10;
        int r = e & 1023;
        int i = r >> 5;
        int j = r & 31;
        float per = (float)(i * MM + j + 2);
        Ct[n * CT_STRIDE + i * ROWP + j] = cosf(TWO_PI * (float)n / per);
    }

    // ---- Phase 1b: R = H[a,b] + H[a,b+1] + H[a+1,b] + H[a+1,b+1]  (contiguous 51.2KB blocks) ----
    {
        const int strideB = DM * DM * MM;        // 12800
        const int strideA = DM * strideB;        // 256000
        const float* H00 = H + (long)A * strideA + (long)B * strideB;
        for (int e = tid; e < DM * DM * MM; e += NT) {
            R[e] = H00[e] + H00[e + strideB] + H00[e + strideA] + H00[e + strideA + strideB];
        }
    }
    __syncthreads();

    // ---- Phase 1c: Gab[i][j] = P[i][j] * Ct[A][i][j] * Ct[B][i][j] ----
    for (int e = tid; e < MM * MM; e += NT) {
        int i = e >> 5, j = e & 31;
        Gab[i * ROWP + j] = P[e] * Ct[A * CT_STRIDE + i * ROWP + j]
                                 * Ct[B * CT_STRIDE + i * ROWP + j];
    }

    // ---- M rows in registers (role: lane == j output of the Linear), fold 1/16 ----
    ull Mreg[16];
    {
        const float* mr = Mw + lane * MM;
        #pragma unroll
        for (int l2 = 0; l2 < 16; l2++) {
            float m0 = mr[2 * l2]     * 0.0625f;
            float m1 = mr[2 * l2 + 1] * 0.0625f;
            Mreg[l2] = (ull)__float_as_uint(m0) | ((ull)__float_as_uint(m1) << 32);
        }
    }
    __syncthreads();

    // ---- Phase 2: warp w owns c in {2w, 2w+1} (warp 9 -> only c=18) ----
    const int c0 = 2 * w;
    const int nc = (c0 + 1 < O) ? 2 : 1;

    // Gabc = Gab * Ct[c]  cached in registers (32 floats packed as 16 x f32x2 per c)
    ull G0[16], G1[16];
    #pragma unroll
    for (int l4 = 0; l4 < 8; l4++) {
        ulonglong2 g  = *reinterpret_cast<const ulonglong2*>(&Gab[lane * ROWP + 4 * l4]);
        ulonglong2 cA = *reinterpret_cast<const ulonglong2*>(&Ct[c0 * CT_STRIDE + lane * ROWP + 4 * l4]);
        G0[2 * l4]     = f2mul(g.x, cA.x);
        G0[2 * l4 + 1] = f2mul(g.y, cA.y);
    }
    if (nc == 2) {
        #pragma unroll
        for (int l4 = 0; l4 < 8; l4++) {
            ulonglong2 g  = *reinterpret_cast<const ulonglong2*>(&Gab[lane * ROWP + 4 * l4]);
            ulonglong2 cB = *reinterpret_cast<const ulonglong2*>(&Ct[(c0 + 1) * CT_STRIDE + lane * ROWP + 4 * l4]);
            G1[2 * l4]     = f2mul(g.x, cB.x);
            G1[2 * l4 + 1] = f2mul(g.y, cB.y);
        }
    }

    float* ws0p = WSs + (w * 2 + 0) * 32;
    float* ws1p = WSs + (w * 2 + 1) * 32;
    float* x0p  = Xs  + (w * 2 + 0) * 32;
    float* x1p  = Xs  + (w * 2 + 1) * 32;

    const long outBase = (long)(A * O + B) * (O * O) * MM;

    for (int d = 0; d < O; d++) {
        // window sums (role: lane == l), share middle row between the two c's
        float rA = R[(c0 * DM + d) * MM + lane]       + R[(c0 * DM + d + 1) * MM + lane];
        float rB = R[((c0 + 1) * DM + d) * MM + lane] + R[((c0 + 1) * DM + d + 1) * MM + lane];
        ws0p[lane] = rA + rB;
        if (nc == 2) {
            float rC = R[((c0 + 2) * DM + d) * MM + lane] + R[((c0 + 2) * DM + d + 1) * MM + lane];
            ws1p[lane] = rB + rC;
        }
        __syncwarp();

        // matvec: x_j = sum_l (M[j,l]/16) * ws_l   (role: lane == j)
        {
            ull a0 = 0, a0b = 0, a1 = 0, a1b = 0;
            #pragma unroll
            for (int l4 = 0; l4 < 8; l4++) {
                ulonglong2 wv0 = *reinterpret_cast<const ulonglong2*>(&ws0p[4 * l4]);
                a0  = f2fma(Mreg[2 * l4],     wv0.x, a0);
                a0b = f2fma(Mreg[2 * l4 + 1], wv0.y, a0b);
                if (nc == 2) {
                    ulonglong2 wv1 = *reinterpret_cast<const ulonglong2*>(&ws1p[4 * l4]);
                    a1  = f2fma(Mreg[2 * l4],     wv1.x, a1);
                    a1b = f2fma(Mreg[2 * l4 + 1], wv1.y, a1b);
                }
            }
            x0p[lane] = f2sum(a0) + f2sum(a0b);
            if (nc == 2) x1p[lane] = f2sum(a1) + f2sum(a1b);
        }
        __syncwarp();

        // main contraction: out_i = sum_j x_j * Gabc[i][j] * Ct[d][i][j]   (role: lane == i)
        {
            ull A0 = 0, A0b = 0, A1 = 0, A1b = 0;
            #pragma unroll
            for (int l4 = 0; l4 < 8; l4++) {
                ulonglong2 cd  = *reinterpret_cast<const ulonglong2*>(&Ct[d * CT_STRIDE + lane * ROWP + 4 * l4]);
                ulonglong2 xv0 = *reinterpret_cast<const ulonglong2*>(&x0p[4 * l4]);
                A0  = f2fma(f2mul(cd.x, G0[2 * l4]),     xv0.x, A0);
                A0b = f2fma(f2mul(cd.y, G0[2 * l4 + 1]), xv0.y, A0b);
                if (nc == 2) {
                    ulonglong2 xv1 = *reinterpret_cast<const ulonglong2*>(&x1p[4 * l4]);
                    A1  = f2fma(f2mul(cd.x, G1[2 * l4]),     xv1.x, A1);
                    A1b = f2fma(f2mul(cd.y, G1[2 * l4 + 1]), xv1.y, A1b);
                }
            }
            out[outBase + ((long)c0 * O + d) * MM + lane] = f2sum(A0) + f2sum(A0b);
            if (nc == 2)
                out[outBase + ((long)(c0 + 1) * O + d) * MM + lane] = f2sum(A1) + f2sum(A1b);
        }
        __syncwarp();
    }
}

extern "C" void kernel_launch(void* const* d_in, const int* in_sizes, int n_in,
                              void* d_out, int out_size)
{
    const float* H  = (const float*)d_in[0];
    const float* Mw = (const float*)d_in[1];
    const float* P  = (const float*)d_in[2];
    float* out = (float*)d_out;

    // Idempotent; not a stream op, safe under graph capture.
    cudaFuncSetAttribute(pm4_kernel, cudaFuncAttributeMaxDynamicSharedMemorySize, SMEM_BYTES);

    pm4_kernel<<<O * O, NT, SMEM_BYTES>>>(H, Mw, P, out);
}

// round 2
// speedup vs baseline: 1.5136x; 1.5136x over previous
#include <cuda_runtime.h>
#include <cstdint>

// Problem constants (D=20, RANK=2 -> o=19 per axis, m=32)
#define O      19
#define DM     20
#define MM     32
#define ROWP   36                    // padded row (floats) -> conflict-free LDS.128
#define CT_STRIDE (MM*ROWP)          // 1152 floats per cos-table slab
#define NT     640                   // 20 warps: (c-pair 0..9) x (d-group 0..1)
#define NITEMS (O*O*2)               // (a,b) x d-half

typedef unsigned long long ull;

// ---- packed f32x2 helpers ----
__device__ __forceinline__ ull f2mul(ull a, ull b) {
    ull r; asm("mul.rn.f32x2 %0, %1, %2;" : "=l"(r) : "l"(a), "l"(b)); return r;
}
__device__ __forceinline__ ull f2fma(ull a, ull b, ull c) {
    ull r; asm("fma.rn.f32x2 %0, %1, %2, %3;" : "=l"(r) : "l"(a), "l"(b), "l"(c)); return r;
}
__device__ __forceinline__ float f2sum(ull v) {
    return __uint_as_float((unsigned)v) + __uint_as_float((unsigned)(v >> 32));
}

// Shared memory layout (floats):
//   Ct  [19][32][36] @ 0      (21888)  Ct[n][i][j] = cos(2*pi*n / (32*i+j+2))
//   R   [20][20][32] @ 21888  (12800)  (a,b)-pair sum of hypervol
//   Gab [32][36]     @ 34688  (1152)   P * Ct[A] * Ct[B]
//   Msc [32][36]     @ 35840  (1152)   M_w / 16 (row-padded)
//   X   [19][10][32] @ 36992  (6080)   x[c, d-dstart, j] for current item
//   WS  [20][32]     @ 43072  (640)    per-warp window-sum staging
#define CT_OFF   0
#define R_OFF    21888
#define GAB_OFF  34688
#define MS_OFF   35840
#define X_OFF    36992
#define WS_OFF   43072
#define SMEM_FLOATS 43712
#define SMEM_BYTES (SMEM_FLOATS * 4)

__global__ void __launch_bounds__(NT, 1)
pm4_kernel(const float* __restrict__ H,   // [20,20,20,20,32]
           const float* __restrict__ Mw,  // [32,32]
           const float* __restrict__ P,   // [32,32]
           float* __restrict__ out)       // [19^4, 32]
{
    extern __shared__ float s[];
    float* Ct  = s + CT_OFF;
    float* R   = s + R_OFF;
    float* Gab = s + GAB_OFF;
    float* Msc = s + MS_OFF;
    float* X   = s + X_OFF;
    float* WS  = s + WS_OFF;

    const int tid  = threadIdx.x;
    const int lane = tid & 31;
    const int w    = tid >> 5;
    const int cp   = w >> 1;          // 0..9
    const int dg   = w & 1;           // 0..1
    const int c0   = 2 * cp;
    const int nc   = (cp == 9) ? 1 : 2;

    const float TWO_PI = 6.28318530717958647692f;

    // ---- once per CTA: cos table + prescaled M ----
    for (int e = tid; e < O * MM * MM; e += NT) {
        int n = e >> 10;
        int r = e & 1023;
        int i = r >> 5;
        int j = r & 31;
        float per = (float)(i * MM + j + 2);
        Ct[n * CT_STRIDE + i * ROWP + j] = cosf(TWO_PI * (float)n / per);
    }
    for (int e = tid; e < MM * MM; e += NT) {
        Msc[(e >> 5) * ROWP + (e & 31)] = Mw[e] * 0.0625f;
    }

    float* wsp = WS + w * 32;

    // ---- persistent loop over items (ab, d-half) ----
    for (int item = blockIdx.x; item < NITEMS; item += gridDim.x) {
        const int ab = item >> 1;
        const int dh = item & 1;
        const int A = ab / O;
        const int B = ab % O;
        const int dstart = dh ? 10 : 0;
        const int dnum   = dh ? 9 : 10;

        __syncthreads();   // previous item fully consumed R/X/Gab

        // R = 2x2 (a,b) window pair-sum, float4-vectorized contiguous loads
        {
            const int strideB = DM * DM * MM;        // 12800 floats
            const int strideA = DM * strideB;
            const float4* H00 = (const float4*)(H + (long)A * strideA + (long)B * strideB);
            const float4* H01 = H00 + strideB / 4;
            const float4* H10 = H00 + strideA / 4;
            const float4* H11 = H10 + strideB / 4;
            float4* R4 = (float4*)R;
            for (int e = tid; e < DM * DM * MM / 4; e += NT) {
                float4 a = H00[e], b = H01[e], c = H10[e], d = H11[e];
                R4[e] = make_float4(a.x + b.x + c.x + d.x,
                                    a.y + b.y + c.y + d.y,
                                    a.z + b.z + c.z + d.z,
                                    a.w + b.w + c.w + d.w);
            }
        }
        // Gab = P * Ct[A] * Ct[B]
        for (int e = tid; e < MM * MM; e += NT) {
            int i = e >> 5, j = e & 31;
            Gab[i * ROWP + j] = P[e] * Ct[A * CT_STRIDE + i * ROWP + j]
                                     * Ct[B * CT_STRIDE + i * ROWP + j];
        }
        __syncthreads();

        // ---- Phase P: all window-sums + matvecs -> X[c][dd][j] ----
        {
            // M rows in registers (phase-local liveness; lane plays role j)
            ull Mreg[16];
            #pragma unroll
            for (int l4 = 0; l4 < 8; l4++) {
                ulonglong2 m = *reinterpret_cast<const ulonglong2*>(&Msc[lane * ROWP + 4 * l4]);
                Mreg[2 * l4] = m.x; Mreg[2 * l4 + 1] = m.y;
            }
            const int npairs = O * dnum;     // (c, dd) pairs
            for (int p = w; p < npairs; p += 20) {
                const int c  = p / dnum;
                const int dd = p - c * dnum;
                const int d  = dstart + dd;
                // window sum over (c..c+1, d..d+1); lane plays role l
                float v = R[(c * DM + d) * MM + lane]
                        + R[(c * DM + d + 1) * MM + lane]
                        + R[((c + 1) * DM + d) * MM + lane]
                        + R[((c + 1) * DM + d + 1) * MM + lane];
                wsp[lane] = v;
                __syncwarp();
                ull a0 = 0, a1 = 0;
                #pragma unroll
                for (int l4 = 0; l4 < 8; l4++) {
                    ulonglong2 wv = *reinterpret_cast<const ulonglong2*>(&wsp[4 * l4]);
                    a0 = f2fma(Mreg[2 * l4],     wv.x, a0);
                    a1 = f2fma(Mreg[2 * l4 + 1], wv.y, a1);
                }
                X[(c * 10 + dd) * 32 + lane] = f2sum(a0) + f2sum(a1);
                __syncwarp();
            }
        }
        __syncthreads();

        // ---- Phase C: contraction. warp = (c-pair, d-group). lane plays role i ----
        {
            // G = Gab * Ct[c] cached in registers
            ull G0[16], G1[16];
            #pragma unroll
            for (int l4 = 0; l4 < 8; l4++) {
                ulonglong2 g  = *reinterpret_cast<const ulonglong2*>(&Gab[lane * ROWP + 4 * l4]);
                ulonglong2 cA = *reinterpret_cast<const ulonglong2*>(&Ct[c0 * CT_STRIDE + lane * ROWP + 4 * l4]);
                G0[2 * l4]     = f2mul(g.x, cA.x);
                G0[2 * l4 + 1] = f2mul(g.y, cA.y);
                if (nc == 2) {
                    ulonglong2 cB = *reinterpret_cast<const ulonglong2*>(&Ct[(c0 + 1) * CT_STRIDE + lane * ROWP + 4 * l4]);
                    G1[2 * l4]     = f2mul(g.x, cB.x);
                    G1[2 * l4 + 1] = f2mul(g.y, cB.y);
                }
            }

            const long outBase = (long)ab * (O * O) * MM;
            for (int dd = dg; dd < dnum; dd += 2) {
                const int d = dstart + dd;
                const float* cdrow = &Ct[d * CT_STRIDE + lane * ROWP];
                const float* xv0p  = &X[(c0 * 10 + dd) * 32];
                const float* xv1p  = &X[((c0 + 1) * 10 + dd) * 32];
                ull A0 = 0, A0b = 0, A1 = 0, A1b = 0;
                #pragma unroll
                for (int l4 = 0; l4 < 8; l4++) {
                    ulonglong2 cd  = *reinterpret_cast<const ulonglong2*>(cdrow + 4 * l4);
                    ulonglong2 xv0 = *reinterpret_cast<const ulonglong2*>(xv0p + 4 * l4);
                    A0  = f2fma(f2mul(cd.x, G0[2 * l4]),     xv0.x, A0);
                    A0b = f2fma(f2mul(cd.y, G0[2 * l4 + 1]), xv0.y, A0b);
                    if (nc == 2) {
                        ulonglong2 xv1 = *reinterpret_cast<const ulonglong2*>(xv1p + 4 * l4);
                        A1  = f2fma(f2mul(cd.x, G1[2 * l4]),     xv1.x, A1);
                        A1b = f2fma(f2mul(cd.y, G1[2 * l4 + 1]), xv1.y, A1b);
                    }
                }
                out[outBase + ((long)c0 * O + d) * MM + lane] = f2sum(A0) + f2sum(A0b);
                if (nc == 2)
                    out[outBase + ((long)(c0 + 1) * O + d) * MM + lane] = f2sum(A1) + f2sum(A1b);
            }
        }
    }
}

extern "C" void kernel_launch(void* const* d_in, const int* in_sizes, int n_in,
                              void* d_out, int out_size)
{
    const float* H  = (const float*)d_in[0];
    const float* Mw = (const float*)d_in[1];
    const float* P  = (const float*)d_in[2];
    float* out = (float*)d_out;

    cudaFuncSetAttribute(pm4_kernel, cudaFuncAttributeMaxDynamicSharedMemorySize, SMEM_BYTES);

    int dev = 0, nsm = 148;
    cudaGetDevice(&dev);
    cudaDeviceGetAttribute(&nsm, cudaDevAttrMultiProcessorCount, dev);
    if (nsm <= 0) nsm = 148;
    if (nsm > NITEMS) nsm = NITEMS;

    pm4_kernel<<<nsm, NT, SMEM_BYTES>>>(H, Mw, P, out);
}